// round 2
// baseline (speedup 1.0000x reference)
#include <cuda_runtime.h>
#include <math.h>

// Problem constants
#define N_B     32
#define C_DIM   384
#define HW      3136        // 56*56
#define M_DIM   8
#define D_MODEL 768
#define E_DIM   768         // 2*C

// ---------------- scratch for clipped KV (allowed: __device__ global) ----------
__device__ float g_kv[N_B * M_DIM * E_DIM];   // [n][m][e], e<384 = K, e>=384 = V

// ================= Kernel 1: kv = clip(gf @ W^T + b, 0, 6) =====================
#define BM 32
#define BN 64
#define BK 32

__global__ __launch_bounds__(256) void kv_gemm_kernel(
    const float* __restrict__ gf,
    const float* __restrict__ W,
    const float* __restrict__ bias)
{
    __shared__ float As[BK][BM + 2];
    __shared__ float Bs[BK][BN + 4];

    const int tid = threadIdx.x;
    const int tx  = tid & 15;
    const int ty  = tid >> 4;
    const int rb  = blockIdx.y * BM;
    const int eb  = blockIdx.x * BN;

    float acc[2][4];
    #pragma unroll
    for (int i = 0; i < 2; i++)
        #pragma unroll
        for (int j = 0; j < 4; j++) acc[i][j] = 0.f;

    for (int kb = 0; kb < D_MODEL; kb += BK) {
        #pragma unroll
        for (int i = 0; i < 4; i++) {
            int idx = tid + i * 256;
            int r  = idx >> 5;
            int kk = idx & 31;
            As[kk][r] = gf[(size_t)(rb + r) * D_MODEL + kb + kk];
        }
        #pragma unroll
        for (int i = 0; i < 8; i++) {
            int idx = tid + i * 256;
            int e  = idx >> 5;
            int kk = idx & 31;
            Bs[kk][e] = W[(size_t)(eb + e) * D_MODEL + kb + kk];
        }
        __syncthreads();

        #pragma unroll
        for (int kk = 0; kk < BK; kk++) {
            float2 av = *(const float2*)&As[kk][ty * 2];
            float4 bv = *(const float4*)&Bs[kk][tx * 4];
            acc[0][0] += av.x * bv.x; acc[0][1] += av.x * bv.y;
            acc[0][2] += av.x * bv.z; acc[0][3] += av.x * bv.w;
            acc[1][0] += av.y * bv.x; acc[1][1] += av.y * bv.y;
            acc[1][2] += av.y * bv.z; acc[1][3] += av.y * bv.w;
        }
        __syncthreads();
    }

    float4 bb = *(const float4*)&bias[eb + tx * 4];
    #pragma unroll
    for (int r = 0; r < 2; r++) {
        float4 o;
        o.x = fminf(fmaxf(acc[r][0] + bb.x, 0.f), 6.f);
        o.y = fminf(fmaxf(acc[r][1] + bb.y, 0.f), 6.f);
        o.z = fminf(fmaxf(acc[r][2] + bb.z, 0.f), 6.f);
        o.w = fminf(fmaxf(acc[r][3] + bb.w, 0.f), 6.f);
        *(float4*)&g_kv[(size_t)(rb + ty * 2 + r) * E_DIM + eb + tx * 4] = o;
    }
}

// ================= Kernel 2: streaming attention + residual ====================
// Thread-per-pixel. Phase 1: stream x (coalesced), accumulate 8 scores/thread.
// Softmax in registers. Phase 2: re-read x in REVERSE channel order (L2-hot),
// add attn@V, store coalesced. Only K/V staged in smem (24 KB) -> ~3 CTA/SM.
#define TILE_P2   224
#define NTHREADS2 224

__global__ __launch_bounds__(NTHREADS2) void attn_kernel(
    const float* __restrict__ x,
    float* __restrict__ out)
{
    __shared__ float Ks[M_DIM * C_DIM];   // [k][c]
    __shared__ float Vs[M_DIM * C_DIM];   // [k][c]

    const int tid = threadIdx.x;
    const int n   = blockIdx.y;
    const int p   = blockIdx.x * TILE_P2 + tid;

    // ---- stage K,V for batch n ----
    {
        const float4* kv4 = (const float4*)(g_kv + (size_t)n * (M_DIM * E_DIM));
        for (int i = tid; i < (M_DIM * E_DIM) / 4; i += NTHREADS2) {
            int m = i / 192;
            int j = i - m * 192;
            float4 v = kv4[i];
            int e = j * 4;
            if (e < C_DIM) *(float4*)&Ks[m * C_DIM + e] = v;
            else           *(float4*)&Vs[m * C_DIM + (e - C_DIM)] = v;
        }
    }
    __syncthreads();

    const float* xp = x + (size_t)n * C_DIM * HW + p;

    // ---- phase 1: scores (stream x once, ascending channels) ----
    float acc[8];
    #pragma unroll
    for (int k = 0; k < 8; k++) acc[k] = 0.f;

    #pragma unroll 2
    for (int c = 0; c < C_DIM; c += 4) {
        float x0 = xp[(size_t)(c + 0) * HW];
        float x1 = xp[(size_t)(c + 1) * HW];
        float x2 = xp[(size_t)(c + 2) * HW];
        float x3 = xp[(size_t)(c + 3) * HW];
        #pragma unroll
        for (int k = 0; k < 8; k++) {
            float4 kk = *(const float4*)&Ks[k * C_DIM + c];
            acc[k] += x0 * kk.x + x1 * kk.y + x2 * kk.z + x3 * kk.w;
        }
    }

    // ---- softmax over k=8, in registers ----
    float mx = acc[0];
    #pragma unroll
    for (int k = 1; k < 8; k++) mx = fmaxf(mx, acc[k]);
    float sum = 0.f;
    #pragma unroll
    for (int k = 0; k < 8; k++) { acc[k] = __expf(acc[k] - mx); sum += acc[k]; }
    float inv = 1.0f / sum;
    #pragma unroll
    for (int k = 0; k < 8; k++) acc[k] *= inv;

    // ---- phase 2: out = x + attn@V (reverse channel order -> L2-hot re-read) ----
    float* op = out + (size_t)n * C_DIM * HW + p;

    #pragma unroll 2
    for (int c = C_DIM - 4; c >= 0; c -= 4) {
        float o0 = xp[(size_t)(c + 0) * HW];
        float o1 = xp[(size_t)(c + 1) * HW];
        float o2 = xp[(size_t)(c + 2) * HW];
        float o3 = xp[(size_t)(c + 3) * HW];
        #pragma unroll
        for (int k = 0; k < 8; k++) {
            float4 vv = *(const float4*)&Vs[k * C_DIM + c];
            o0 += acc[k] * vv.x; o1 += acc[k] * vv.y;
            o2 += acc[k] * vv.z; o3 += acc[k] * vv.w;
        }
        op[(size_t)(c + 0) * HW] = o0;
        op[(size_t)(c + 1) * HW] = o1;
        op[(size_t)(c + 2) * HW] = o2;
        op[(size_t)(c + 3) * HW] = o3;
    }
}

// ================= launch ======================================================
extern "C" void kernel_launch(void* const* d_in, const int* in_sizes, int n_in,
                              void* d_out, int out_size)
{
    const float* x  = (const float*)d_in[0];
    const float* gf = (const float*)d_in[1];
    const float* W  = (const float*)d_in[2];
    const float* b  = (const float*)d_in[3];
    float* out = (float*)d_out;

    kv_gemm_kernel<<<dim3(E_DIM / BN, (N_B * M_DIM) / BM), 256>>>(gf, W, b);
    attn_kernel<<<dim3(HW / TILE_P2, N_B), NTHREADS2>>>(x, out);
}